// round 4
// baseline (speedup 1.0000x reference)
#include <cuda_runtime.h>
#include <math.h>

// CropAndResize: x [B,H,W,C=4] fp32, boxes [B,4] (y1,x1,y2,x2 in [0,1]),
// output [B,crop,crop,4] fp32 bilinear.
//
// Separable formulation, one block per (output row, batch):
//   in_y depends only on the output row -> source rows t/b are block-uniform.
//   1) cooperatively load x[t, lo..hi] and x[b, lo..hi] (fully coalesced,
//      each 128B line touched once), vertical-lerp into a smem row
//   2) per-pixel horizontal lerp via 2 LDS.128 gathers, coalesced STG.128.
// This removes the 4-way scattered-gather L1tex replay storm of the naive
// kernel (the measured bottleneck).

#define TPB 256
#define VROW_MAX 1040   // worst-case span (<=1024) + guard margin

__global__ __launch_bounds__(TPB)
void crop_resize_rows_kernel(const float* __restrict__ x,
                             const float* __restrict__ boxes,
                             float* __restrict__ out,
                             int H, int W, int crop) {
    __shared__ float4 vrow[VROW_MAX];

    const int r = blockIdx.x;   // output row
    const int b = blockIdx.y;   // batch
    const int tid = threadIdx.x;

    const float y1 = boxes[b * 4 + 0];
    const float x1 = boxes[b * 4 + 1];
    const float y2 = boxes[b * 4 + 2];
    const float x2 = boxes[b * 4 + 3];

    const float inv = 1.0f / (float)(crop - 1);
    const float hm1 = (float)(H - 1);
    const float wm1 = (float)(W - 1);
    const float dy = (y2 - y1) * hm1;
    const float dx = (x2 - x1) * wm1;
    const float oy = y1 * hm1;
    const float ox = x1 * wm1;

    float4* __restrict__ outrow =
        (float4*)(out) + ((size_t)b * crop + r) * crop;

    // ---- vertical position for this output row (block-uniform) ----
    const float in_y = fmaf((float)r * inv, dy, oy);
    const bool valid_y = (in_y >= 0.0f) && (in_y <= hm1);

    if (!valid_y) {
        const float4 z = make_float4(0.f, 0.f, 0.f, 0.f);
        for (int c = tid; c < crop; c += TPB) outrow[c] = z;
        return;  // uniform across block: safe before __syncthreads
    }

    const float top_f = floorf(in_y);
    const float yl = in_y - top_f;
    int t = min(max((int)top_f, 0), H - 1);
    int bo = min(t + 1, H - 1);

    // ---- x-span covered by this box (block-uniform), with safety margin ----
    const float inx_min = fminf(ox, ox + dx);
    const float inx_max = fmaxf(ox, ox + dx);
    int lo = max(0, (int)floorf(inx_min) - 1);
    int hi = min(W - 1, (int)floorf(inx_max) + 2);
    const int span = hi - lo + 1;   // <= W, fits VROW_MAX

    // ---- pass 1: coalesced load of rows t and bo over [lo..hi], v-lerp ----
    const float4* __restrict__ rowT =
        (const float4*)(x) + ((size_t)b * H + t) * W + lo;
    const float4* __restrict__ rowB =
        (const float4*)(x) + ((size_t)b * H + bo) * W + lo;

    for (int i = tid; i < span; i += TPB) {
        const float4 vt = __ldg(rowT + i);
        const float4 vb = __ldg(rowB + i);
        float4 v;
        v.x = fmaf(vb.x - vt.x, yl, vt.x);
        v.y = fmaf(vb.y - vt.y, yl, vt.y);
        v.z = fmaf(vb.z - vt.z, yl, vt.z);
        v.w = fmaf(vb.w - vt.w, yl, vt.w);
        vrow[i] = v;
    }
    __syncthreads();

    // ---- pass 2: horizontal lerp from smem, coalesced store ----
    for (int c = tid; c < crop; c += TPB) {
        const float in_x = fmaf((float)c * inv, dx, ox);
        const bool valid_x = (in_x >= 0.0f) && (in_x <= wm1);

        float4 res = make_float4(0.f, 0.f, 0.f, 0.f);
        if (valid_x) {
            const float left_f = floorf(in_x);
            const float xl = in_x - left_f;
            int l = min(max((int)left_f, 0), W - 1);
            int rr = min(l + 1, W - 1);
            int sl = min(max(l - lo, 0), span - 1);
            int sr = min(max(rr - lo, 0), span - 1);
            const float4 vl = vrow[sl];
            const float4 vr = vrow[sr];
            res.x = fmaf(vr.x - vl.x, xl, vl.x);
            res.y = fmaf(vr.y - vl.y, xl, vl.y);
            res.z = fmaf(vr.z - vl.z, xl, vl.z);
            res.w = fmaf(vr.w - vl.w, xl, vl.w);
        }
        outrow[c] = res;
    }
}

extern "C" void kernel_launch(void* const* d_in, const int* in_sizes, int n_in,
                              void* d_out, int out_size) {
    const float* x     = (const float*)d_in[0];
    const float* boxes = (const float*)d_in[1];
    float* out = (float*)d_out;

    const int B = in_sizes[1] / 4;          // boxes is [B,4]
    const int C = 4;
    const long long hw = (long long)in_sizes[0] / ((long long)B * C);
    int H = (int)(sqrt((double)hw) + 0.5);
    int W = H;
    const long long cc = (long long)out_size / ((long long)B * C);
    int crop = (int)(sqrt((double)cc) + 0.5);

    dim3 grid(crop, B);
    crop_resize_rows_kernel<<<grid, TPB>>>(x, boxes, out, H, W, crop);
}